// round 7
// baseline (speedup 1.0000x reference)
#include <cuda_runtime.h>

// Problem constants (fixed: midis_out is (16, 11, 65536) fp32, LST=64)
#define NB      16
#define NI      11
#define NT      65536
#define LSTLEN  64
#define CHUNK   512
#define NTB     (CHUNK / LSTLEN)    // 8 time-blocks per CTA
#define THREADS 256
#define NWARP   (THREADS / 32)
#define NCHUNK  (NT / CHUNK)        // 128
#define VEC4    (NI * CHUNK / 4)    // 1408 float4 per tile
#define NTASK   (NI * NTB)          // 88 time-block tasks
#define NGRP    (NTASK / 4)         // 22 groups of 4 tasks

__device__ __forceinline__ void ce(float& a, float& b) {
    const float lo = fminf(a, b), hi = fmaxf(a, b);
    a = lo; b = hi;
}

// Optimal 11-input sorting network (35 CE, depth 8), ascending.
__device__ __forceinline__ void sort11(float z[NI]) {
    ce(z[0],z[9]); ce(z[1],z[6]); ce(z[2],z[4]); ce(z[3],z[7]); ce(z[5],z[8]);
    ce(z[0],z[1]); ce(z[3],z[5]); ce(z[4],z[10]); ce(z[6],z[9]); ce(z[7],z[8]);
    ce(z[1],z[3]); ce(z[2],z[5]); ce(z[4],z[7]); ce(z[8],z[10]);
    ce(z[0],z[4]); ce(z[1],z[2]); ce(z[3],z[7]); ce(z[5],z[9]); ce(z[6],z[8]);
    ce(z[0],z[1]); ce(z[2],z[6]); ce(z[4],z[5]); ce(z[7],z[8]); ce(z[9],z[10]);
    ce(z[2],z[4]); ce(z[3],z[6]); ce(z[5],z[7]); ce(z[8],z[9]);
    ce(z[1],z[2]); ce(z[3],z[4]); ce(z[5],z[6]); ce(z[7],z[8]);
    ce(z[2],z[3]); ce(z[4],z[5]); ce(z[6],z[7]);
}

// Exact sparsemax over 11 values; returns NEGATED tau (destroys z).
// cond_k: 1 + k*z_(k) > csum_k holds exactly for k <= k_z (prefix-monotone),
// so k_z = last k with cond true, csum_{k_z} = cs at that k.
// -tau = (1 - csum_{k_z}) / k_z.
__device__ __forceinline__ float sparsemax11_negtau(float z[NI]) {
    sort11(z);
    float cs = 0.0f, sel = 0.0f, cnt = 1.0f;
    #pragma unroll
    for (int k = 1; k <= NI; ++k) {
        const float zk = z[NI - k];                    // k-th largest
        cs += zk;
        const bool c = fmaf((float)k, zk, 1.0f) > cs;  // always true at k=1
        sel = c ? cs : sel;
        cnt = c ? (float)k : cnt;
    }
    return __fdividef(1.0f - sel, cnt);
}

__global__ __launch_bounds__(THREADS, 6)
void multiply_sparsemax_kernel(const float* __restrict__ in,
                               float* __restrict__ out)
{
    __shared__ __align__(16) float xs[NI * CHUNK];   // 22528 B tile
    __shared__ float ntau_time[NTASK];               // -tau per (inst, 64-block)
    __shared__ __align__(16) float ntau_inst[CHUNK]; // -tau per time column

    const int tid  = threadIdx.x;
    const int wid  = tid >> 5;
    const int lane = tid & 31;

    const int b = blockIdx.x / NCHUNK;
    const int c = blockIdx.x % NCHUNK;
    const unsigned base = (unsigned)(b * NI) * NT + (unsigned)(c * CHUNK);

    // ---- Load tile: 11 rows x 512 floats, float4-coalesced ----
    #pragma unroll
    for (int idx = tid; idx < VEC4; idx += THREADS) {
        const int i  = idx >> 7;
        const int t4 = idx & 127;
        *(float4*)(xs + i * CHUNK + t4 * 4) =
            *((const float4*)(in + base + (unsigned)(i * NT)) + t4);
    }
    __syncthreads();

    // ---- Phase A: tau over 64-length time blocks ----
    // 4 tasks/warp (8-lane segments, 8 elems/lane). Michelot from the safe
    // warm start tau0 = max-1 (tau* >= max-1 always). 2 unconditional
    // iterations, then a convergence-checked guard loop: the check IS a full
    // Michelot pass, so exactness is guaranteed regardless of warm count.
    {
        const int seg = lane >> 3;
        const int sl  = lane & 7;
        for (int g = wid; g < NGRP; g += NWARP) {
            const int task = g * 4 + seg;
            const float* p = xs + (task >> 3) * CHUNK + (task & 7) * LSTLEN + sl * 8;
            const float4 v0 = *(const float4*)p;
            const float4 v1 = *(const float4*)(p + 4);
            const float z0 = v0.x, z1 = v0.y, z2 = v0.z, z3 = v0.w;
            const float z4 = v1.x, z5 = v1.y, z6 = v1.z, z7 = v1.w;

            float m = fmaxf(fmaxf(fmaxf(z0, z1), fmaxf(z2, z3)),
                            fmaxf(fmaxf(z4, z5), fmaxf(z6, z7)));
            #pragma unroll
            for (int o = 4; o; o >>= 1)
                m = fmaxf(m, __shfl_xor_sync(0xFFFFFFFFu, m, o));

            float tau = m - 1.0f;
            float cf  = 0.0f;

            #pragma unroll
            for (int it = 0; it < 2; ++it) {
                float ss = 0.0f; cf = 0.0f;
                if (z0 > tau) { ss += z0; cf += 1.0f; }
                if (z1 > tau) { ss += z1; cf += 1.0f; }
                if (z2 > tau) { ss += z2; cf += 1.0f; }
                if (z3 > tau) { ss += z3; cf += 1.0f; }
                if (z4 > tau) { ss += z4; cf += 1.0f; }
                if (z5 > tau) { ss += z5; cf += 1.0f; }
                if (z6 > tau) { ss += z6; cf += 1.0f; }
                if (z7 > tau) { ss += z7; cf += 1.0f; }
                #pragma unroll
                for (int o = 4; o; o >>= 1) {
                    ss += __shfl_xor_sync(0xFFFFFFFFu, ss, o);
                    cf += __shfl_xor_sync(0xFFFFFFFFu, cf, o);
                }
                tau = __fdividef(ss - 1.0f, cf);
            }

            int k = (int)cf;
            #pragma unroll 1
            for (;;) {
                float ss = 0.0f, c2 = 0.0f;
                if (z0 > tau) { ss += z0; c2 += 1.0f; }
                if (z1 > tau) { ss += z1; c2 += 1.0f; }
                if (z2 > tau) { ss += z2; c2 += 1.0f; }
                if (z3 > tau) { ss += z3; c2 += 1.0f; }
                if (z4 > tau) { ss += z4; c2 += 1.0f; }
                if (z5 > tau) { ss += z5; c2 += 1.0f; }
                if (z6 > tau) { ss += z6; c2 += 1.0f; }
                if (z7 > tau) { ss += z7; c2 += 1.0f; }
                #pragma unroll
                for (int o = 4; o; o >>= 1) {
                    ss += __shfl_xor_sync(0xFFFFFFFFu, ss, o);
                    c2 += __shfl_xor_sync(0xFFFFFFFFu, c2, o);
                }
                const int kn = (int)c2;
                const bool conv = (kn >= k);         // support stable
                if (__all_sync(0xFFFFFFFFu, conv)) break;
                if (!conv) { tau = __fdividef(ss - 1.0f, c2); k = kn; }
            }
            if (sl == 0) ntau_time[task] = -tau;
        }
    }

    // ---- Phase B: instrument sparsemax (sort + count-form scan, branch-free).
    //      Depends only on xs (already synced) -> runs BEFORE the barrier so
    //      Phase-A warp skew is hidden under this compute. ----
    {
        const int t0 = tid * 2;              // 2 adjacent columns
        float za[NI], zb[NI];
        #pragma unroll
        for (int i = 0; i < NI; ++i) {
            const float2 v = *(const float2*)(xs + i * CHUNK + t0);
            za[i] = v.x; zb[i] = v.y;
        }
        const float nta = sparsemax11_negtau(za);
        const float ntb = sparsemax11_negtau(zb);
        *(float2*)(ntau_inst + t0) = make_float2(nta, ntb);
    }

    __syncthreads();                         // ntau_time + ntau_inst visible

    // ---- Phase C: float4 epilogue, STG.128 stores. Per thread: column group
    //      t4 is FIXED -> the 4 instrument taus are one hoisted LDS.128 and
    //      the time-block index is fixed too (only the row varies). ----
    {
        const int t4 = (tid & 127) * 4;
        const int blkb = t4 >> 6;                          // fixed per thread
        const float4 ni = *(const float4*)(ntau_inst + t4); // 4 inst taus
        #pragma unroll
        for (int idx = tid; idx < VEC4; idx += THREADS) {
            const int i = idx >> 7;
            const float nt = ntau_time[i * NTB + blkb];    // broadcast LDS
            const float4 v = *(const float4*)(xs + i * CHUNK + t4);
            float4 r;
            r.x = fmaxf(v.x + ni.x, 0.0f) * fmaxf(v.x + nt, 0.0f);
            r.y = fmaxf(v.y + ni.y, 0.0f) * fmaxf(v.y + nt, 0.0f);
            r.z = fmaxf(v.z + ni.z, 0.0f) * fmaxf(v.z + nt, 0.0f);
            r.w = fmaxf(v.w + ni.w, 0.0f) * fmaxf(v.w + nt, 0.0f);
            *((float4*)(out + base + (unsigned)(i * NT)) + (t4 >> 2)) = r;
        }
    }
}

extern "C" void kernel_launch(void* const* d_in, const int* in_sizes, int n_in,
                              void* d_out, int out_size)
{
    const float* in = (const float*)d_in[0];
    float* out = (float*)d_out;
    multiply_sparsemax_kernel<<<NB * NCHUNK, THREADS>>>(in, out);
}

// round 8
// speedup vs baseline: 1.0255x; 1.0255x over previous
#include <cuda_runtime.h>

// Problem constants (fixed: midis_out is (16, 11, 65536) fp32, LST=64)
#define NB      16
#define NI      11
#define NT      65536
#define LSTLEN  64
#define CHUNK   512
#define NTB     (CHUNK / LSTLEN)    // 8 time-blocks per CTA
#define THREADS 256
#define NWARP   (THREADS / 32)
#define NCHUNK  (NT / CHUNK)        // 128
#define VEC4    (NI * CHUNK / 4)    // 1408 float4 per tile
#define NTASK   (NI * NTB)          // 88 time-block tasks
#define NGRP    (NTASK / 4)         // 22 groups of 4 tasks

__device__ __forceinline__ void ce(float& a, float& b) {
    const float lo = fminf(a, b), hi = fmaxf(a, b);
    a = lo; b = hi;
}

// Optimal 11-input sorting network (35 CE, depth 8), ascending.
__device__ __forceinline__ void sort11(float z[NI]) {
    ce(z[0],z[9]); ce(z[1],z[6]); ce(z[2],z[4]); ce(z[3],z[7]); ce(z[5],z[8]);
    ce(z[0],z[1]); ce(z[3],z[5]); ce(z[4],z[10]); ce(z[6],z[9]); ce(z[7],z[8]);
    ce(z[1],z[3]); ce(z[2],z[5]); ce(z[4],z[7]); ce(z[8],z[10]);
    ce(z[0],z[4]); ce(z[1],z[2]); ce(z[3],z[7]); ce(z[5],z[9]); ce(z[6],z[8]);
    ce(z[0],z[1]); ce(z[2],z[6]); ce(z[4],z[5]); ce(z[7],z[8]); ce(z[9],z[10]);
    ce(z[2],z[4]); ce(z[3],z[6]); ce(z[5],z[7]); ce(z[8],z[9]);
    ce(z[1],z[2]); ce(z[3],z[4]); ce(z[5],z[6]); ce(z[7],z[8]);
    ce(z[2],z[3]); ce(z[4],z[5]); ce(z[6],z[7]);
}

// Exact sparsemax tau over 11 values (destroys z).
// tau* = max_{k=1..d} (csum_k - 1)/k over the DESCENDING cumsum:
// for any k-prefix S, sum_{i in S} max(z_i - tau_S, 0) >= sum_{i in S}(z_i - tau_S) = 1
// => tau_S <= tau*, with equality at the true support size. 3 ops per k, no divide.
__device__ __forceinline__ float sparsemax11_tau(float z[NI]) {
    sort11(z);
    float cs  = z[NI - 1];          // largest
    float tau = cs - 1.0f;          // k = 1 candidate
    #pragma unroll
    for (int k = 2; k <= NI; ++k) {
        cs += z[NI - k];            // k-th largest
        const float rk = 1.0f / (float)k;          // compile-time constant
        tau = fmaxf(tau, fmaf(cs, rk, -rk));       // (cs-1)/k
    }
    return tau;
}

__global__ __launch_bounds__(THREADS, 6)
void multiply_sparsemax_kernel(const float* __restrict__ in,
                               float* __restrict__ out)
{
    __shared__ __align__(16) float xs[NI * CHUNK];  // 22528 B tile
    __shared__ float tau_time[NTASK];               // tau per (inst, 64-block)

    const int tid  = threadIdx.x;
    const int wid  = tid >> 5;
    const int lane = tid & 31;

    const int b = blockIdx.x / NCHUNK;
    const int c = blockIdx.x % NCHUNK;
    const unsigned base = (unsigned)(b * NI) * NT + (unsigned)(c * CHUNK);

    // ---- Load tile: 11 rows x 512 floats, float4-coalesced ----
    #pragma unroll
    for (int idx = tid; idx < VEC4; idx += THREADS) {
        const int i  = idx >> 7;
        const int t4 = idx & 127;
        *(float4*)(xs + i * CHUNK + t4 * 4) =
            *((const float4*)(in + base + (unsigned)(i * NT)) + t4);
    }
    __syncthreads();

    // ---- Phase A: tau over 64-length time blocks ----
    // 4 tasks/warp (8-lane segments, 8 elems/lane). Michelot from the safe
    // warm start tau0 = max-1 (tau* >= max-1 always). 2 unconditional
    // iterations, then a convergence-checked guard loop: the check IS a full
    // Michelot pass, so exactness holds regardless of warm count.
    {
        const int seg = lane >> 3;
        const int sl  = lane & 7;
        for (int g = wid; g < NGRP; g += NWARP) {
            const int task = g * 4 + seg;
            const float* p = xs + (task >> 3) * CHUNK + (task & 7) * LSTLEN + sl * 8;
            const float4 v0 = *(const float4*)p;
            const float4 v1 = *(const float4*)(p + 4);
            const float z0 = v0.x, z1 = v0.y, z2 = v0.z, z3 = v0.w;
            const float z4 = v1.x, z5 = v1.y, z6 = v1.z, z7 = v1.w;

            float m = fmaxf(fmaxf(fmaxf(z0, z1), fmaxf(z2, z3)),
                            fmaxf(fmaxf(z4, z5), fmaxf(z6, z7)));
            #pragma unroll
            for (int o = 4; o; o >>= 1)
                m = fmaxf(m, __shfl_xor_sync(0xFFFFFFFFu, m, o));

            float tau = m - 1.0f;
            float cf  = 0.0f;

            #pragma unroll
            for (int it = 0; it < 2; ++it) {
                float ss = 0.0f; cf = 0.0f;
                if (z0 > tau) { ss += z0; cf += 1.0f; }
                if (z1 > tau) { ss += z1; cf += 1.0f; }
                if (z2 > tau) { ss += z2; cf += 1.0f; }
                if (z3 > tau) { ss += z3; cf += 1.0f; }
                if (z4 > tau) { ss += z4; cf += 1.0f; }
                if (z5 > tau) { ss += z5; cf += 1.0f; }
                if (z6 > tau) { ss += z6; cf += 1.0f; }
                if (z7 > tau) { ss += z7; cf += 1.0f; }
                #pragma unroll
                for (int o = 4; o; o >>= 1) {
                    ss += __shfl_xor_sync(0xFFFFFFFFu, ss, o);
                    cf += __shfl_xor_sync(0xFFFFFFFFu, cf, o);
                }
                tau = __fdividef(ss - 1.0f, cf);
            }

            int k = (int)cf;
            #pragma unroll 1
            for (;;) {
                float ss = 0.0f, c2 = 0.0f;
                if (z0 > tau) { ss += z0; c2 += 1.0f; }
                if (z1 > tau) { ss += z1; c2 += 1.0f; }
                if (z2 > tau) { ss += z2; c2 += 1.0f; }
                if (z3 > tau) { ss += z3; c2 += 1.0f; }
                if (z4 > tau) { ss += z4; c2 += 1.0f; }
                if (z5 > tau) { ss += z5; c2 += 1.0f; }
                if (z6 > tau) { ss += z6; c2 += 1.0f; }
                if (z7 > tau) { ss += z7; c2 += 1.0f; }
                #pragma unroll
                for (int o = 4; o; o >>= 1) {
                    ss += __shfl_xor_sync(0xFFFFFFFFu, ss, o);
                    c2 += __shfl_xor_sync(0xFFFFFFFFu, c2, o);
                }
                const int kn = (int)c2;
                const bool conv = (kn >= k);         // support stable
                if (__all_sync(0xFFFFFFFFu, conv)) break;
                if (!conv) { tau = __fdividef(ss - 1.0f, c2); k = kn; }
            }
            if (sl == 0) tau_time[task] = tau;
        }
    }

    // ---- Phase B: instrument sparsemax (sort + max-formula, branch-free).
    //      Depends only on xs (already synced) -> runs BEFORE the barrier so
    //      Phase-A warp skew is hidden under this compute. ----
    const int t0 = tid * 2;                  // 2 adjacent columns
    float ta, tb2;
    {
        float za[NI], zb[NI];
        #pragma unroll
        for (int i = 0; i < NI; ++i) {
            const float2 v = *(const float2*)(xs + i * CHUNK + t0);
            za[i] = v.x; zb[i] = v.y;
        }
        ta  = sparsemax11_tau(za);           // destroys za
        tb2 = sparsemax11_tau(zb);           // destroys zb
    }

    __syncthreads();                         // tau_time now visible

    // ---- Phase C: fused epilogue straight to gmem (R5 layout) ----
    {
        const int blkb = wid;                // t0>>6 == tid>>5 (uniform/warp)
        const float* px = xs + t0;
        float* po = out + base + (unsigned)t0;
        #pragma unroll
        for (int i = 0; i < NI; ++i) {
            const float  tt = tau_time[i * NTB + blkb];  // broadcast LDS
            const float2 v  = *(const float2*)(px + i * CHUNK);
            float2 r;
            r.x = fmaxf(v.x - ta,  0.0f) * fmaxf(v.x - tt, 0.0f);
            r.y = fmaxf(v.y - tb2, 0.0f) * fmaxf(v.y - tt, 0.0f);
            *(float2*)(po + (unsigned)(i * NT)) = r;
        }
    }
}

extern "C" void kernel_launch(void* const* d_in, const int* in_sizes, int n_in,
                              void* d_out, int out_size)
{
    const float* in = (const float*)d_in[0];
    float* out = (float*)d_out;
    multiply_sparsemax_kernel<<<NB * NCHUNK, THREADS>>>(in, out);
}

// round 9
// speedup vs baseline: 1.0381x; 1.0123x over previous
#include <cuda_runtime.h>
#include <cstdint>

// Problem constants (fixed: midis_out is (16, 11, 65536) fp32, LST=64)
#define NB      16
#define NI      11
#define NT      65536
#define LSTLEN  64
#define CHUNK   512
#define NTB     (CHUNK / LSTLEN)    // 8 time-blocks per CTA
#define THREADS 256
#define NWARP   (THREADS / 32)
#define NCHUNK  (NT / CHUNK)        // 128
#define NTASK   (NI * NTB)          // 88 time-block tasks
#define NGRP    (NTASK / 4)         // 22 groups of 4 tasks
#define ROW_BYTES  (CHUNK * 4)      // 2048 B per tile row
#define TILE_BYTES (NI * ROW_BYTES) // 22528 B

__device__ __forceinline__ void ce(float& a, float& b) {
    const float lo = fminf(a, b), hi = fmaxf(a, b);
    a = lo; b = hi;
}

// Optimal 11-input sorting network (35 CE, depth 8), ascending.
__device__ __forceinline__ void sort11(float z[NI]) {
    ce(z[0],z[9]); ce(z[1],z[6]); ce(z[2],z[4]); ce(z[3],z[7]); ce(z[5],z[8]);
    ce(z[0],z[1]); ce(z[3],z[5]); ce(z[4],z[10]); ce(z[6],z[9]); ce(z[7],z[8]);
    ce(z[1],z[3]); ce(z[2],z[5]); ce(z[4],z[7]); ce(z[8],z[10]);
    ce(z[0],z[4]); ce(z[1],z[2]); ce(z[3],z[7]); ce(z[5],z[9]); ce(z[6],z[8]);
    ce(z[0],z[1]); ce(z[2],z[6]); ce(z[4],z[5]); ce(z[7],z[8]); ce(z[9],z[10]);
    ce(z[2],z[4]); ce(z[3],z[6]); ce(z[5],z[7]); ce(z[8],z[9]);
    ce(z[1],z[2]); ce(z[3],z[4]); ce(z[5],z[6]); ce(z[7],z[8]);
    ce(z[2],z[3]); ce(z[4],z[5]); ce(z[6],z[7]);
}

// Exact sparsemax tau over 11 values (destroys z).
// tau* = max_{k=1..d} (csum_k - 1)/k over the DESCENDING cumsum.
__device__ __forceinline__ float sparsemax11_tau(float z[NI]) {
    sort11(z);
    float cs  = z[NI - 1];
    float tau = cs - 1.0f;
    #pragma unroll
    for (int k = 2; k <= NI; ++k) {
        cs += z[NI - k];
        const float rk = 1.0f / (float)k;          // compile-time constant
        tau = fmaxf(tau, fmaf(cs, rk, -rk));       // (cs-1)/k
    }
    return tau;
}

__device__ __forceinline__ void mbar_wait_parity0(uint32_t mbar_addr) {
    uint32_t done;
    asm volatile(
        "{\n\t.reg .pred p;\n\t"
        "mbarrier.try_wait.parity.acquire.cta.shared::cta.b64 p, [%1], 0;\n\t"
        "selp.b32 %0, 1, 0, p;\n\t}"
        : "=r"(done) : "r"(mbar_addr) : "memory");
    if (!done) {
        asm volatile(
            "{\n\t.reg .pred P1;\n\t"
            "WAIT_LOOP_%=:\n\t"
            "mbarrier.try_wait.parity.acquire.cta.shared::cta.b64 P1, [%0], 0, 0x989680;\n\t"
            "@P1 bra.uni WAIT_DONE_%=;\n\t"
            "bra.uni WAIT_LOOP_%=;\n\t"
            "WAIT_DONE_%=:\n\t}"
            :: "r"(mbar_addr) : "memory");
    }
}

__global__ __launch_bounds__(THREADS, 6)
void multiply_sparsemax_kernel(const float* __restrict__ in,
                               float* __restrict__ out)
{
    __shared__ __align__(16) float xs[NI * CHUNK];  // 22528 B tile
    __shared__ float tau_time[NTASK];               // tau per (inst, 64-block)
    __shared__ __align__(8) unsigned long long mbar;

    const int tid  = threadIdx.x;
    const int wid  = tid >> 5;
    const int lane = tid & 31;

    const int b = blockIdx.x / NCHUNK;
    const int c = blockIdx.x % NCHUNK;
    const unsigned base = (unsigned)(b * NI) * NT + (unsigned)(c * CHUNK);

    // ---- Load tile via bulk-async copy (async proxy writes SMEM directly;
    //      no LDG/STS issue, no register round-trip). 11 rows x 2048 B. ----
    const uint32_t mbar_addr = (uint32_t)__cvta_generic_to_shared(&mbar);
    const uint32_t xs_addr   = (uint32_t)__cvta_generic_to_shared(xs);
    if (tid == 0)
        asm volatile("mbarrier.init.shared.b64 [%0], 1;" :: "r"(mbar_addr) : "memory");
    __syncthreads();
    if (tid == 0) {
        asm volatile("mbarrier.arrive.expect_tx.shared.b64 _, [%0], %1;"
                     :: "r"(mbar_addr), "r"((uint32_t)TILE_BYTES) : "memory");
        const float* src = in + base;
        #pragma unroll
        for (int i = 0; i < NI; ++i) {
            asm volatile(
                "cp.async.bulk.shared::cluster.global.mbarrier::complete_tx::bytes "
                "[%0], [%1], %2, [%3];"
                :: "r"(xs_addr + (uint32_t)(i * ROW_BYTES)),
                   "l"(src + (size_t)i * NT),
                   "r"((uint32_t)ROW_BYTES),
                   "r"(mbar_addr) : "memory");
        }
    }
    mbar_wait_parity0(mbar_addr);   // tile resident (acquire orders LDS after)

    // ---- Phase A: tau over 64-length time blocks ----
    // 4 tasks/warp (8-lane segments, 8 elems/lane). Michelot from the safe
    // warm start tau0 = max-1; 2 unconditional iterations + convergence-
    // checked guard loop (the check IS a full Michelot pass -> exact).
    {
        const int seg = lane >> 3;
        const int sl  = lane & 7;
        for (int g = wid; g < NGRP; g += NWARP) {
            const int task = g * 4 + seg;
            const float* p = xs + (task >> 3) * CHUNK + (task & 7) * LSTLEN + sl * 8;
            const float4 v0 = *(const float4*)p;
            const float4 v1 = *(const float4*)(p + 4);
            const float z0 = v0.x, z1 = v0.y, z2 = v0.z, z3 = v0.w;
            const float z4 = v1.x, z5 = v1.y, z6 = v1.z, z7 = v1.w;

            float m = fmaxf(fmaxf(fmaxf(z0, z1), fmaxf(z2, z3)),
                            fmaxf(fmaxf(z4, z5), fmaxf(z6, z7)));
            #pragma unroll
            for (int o = 4; o; o >>= 1)
                m = fmaxf(m, __shfl_xor_sync(0xFFFFFFFFu, m, o));

            float tau = m - 1.0f;
            float cf  = 0.0f;

            #pragma unroll
            for (int it = 0; it < 2; ++it) {
                float ss = 0.0f; cf = 0.0f;
                if (z0 > tau) { ss += z0; cf += 1.0f; }
                if (z1 > tau) { ss += z1; cf += 1.0f; }
                if (z2 > tau) { ss += z2; cf += 1.0f; }
                if (z3 > tau) { ss += z3; cf += 1.0f; }
                if (z4 > tau) { ss += z4; cf += 1.0f; }
                if (z5 > tau) { ss += z5; cf += 1.0f; }
                if (z6 > tau) { ss += z6; cf += 1.0f; }
                if (z7 > tau) { ss += z7; cf += 1.0f; }
                #pragma unroll
                for (int o = 4; o; o >>= 1) {
                    ss += __shfl_xor_sync(0xFFFFFFFFu, ss, o);
                    cf += __shfl_xor_sync(0xFFFFFFFFu, cf, o);
                }
                tau = __fdividef(ss - 1.0f, cf);
            }

            int k = (int)cf;
            #pragma unroll 1
            for (;;) {
                float ss = 0.0f, c2 = 0.0f;
                if (z0 > tau) { ss += z0; c2 += 1.0f; }
                if (z1 > tau) { ss += z1; c2 += 1.0f; }
                if (z2 > tau) { ss += z2; c2 += 1.0f; }
                if (z3 > tau) { ss += z3; c2 += 1.0f; }
                if (z4 > tau) { ss += z4; c2 += 1.0f; }
                if (z5 > tau) { ss += z5; c2 += 1.0f; }
                if (z6 > tau) { ss += z6; c2 += 1.0f; }
                if (z7 > tau) { ss += z7; c2 += 1.0f; }
                #pragma unroll
                for (int o = 4; o; o >>= 1) {
                    ss += __shfl_xor_sync(0xFFFFFFFFu, ss, o);
                    c2 += __shfl_xor_sync(0xFFFFFFFFu, c2, o);
                }
                const int kn = (int)c2;
                const bool conv = (kn >= k);
                if (__all_sync(0xFFFFFFFFu, conv)) break;
                if (!conv) { tau = __fdividef(ss - 1.0f, c2); k = kn; }
            }
            if (sl == 0) tau_time[task] = tau;
        }
    }

    // ---- Phase B: instrument sparsemax (sort + max-formula, branch-free).
    //      Depends only on xs -> runs BEFORE the barrier to hide A's skew. ----
    const int t0 = tid * 2;
    float ta, tb2;
    {
        float za[NI], zb[NI];
        #pragma unroll
        for (int i = 0; i < NI; ++i) {
            const float2 v = *(const float2*)(xs + i * CHUNK + t0);
            za[i] = v.x; zb[i] = v.y;
        }
        ta  = sparsemax11_tau(za);
        tb2 = sparsemax11_tau(zb);
    }

    __syncthreads();                         // tau_time now visible

    // ---- Phase C: fused epilogue straight to gmem ----
    {
        const int blkb = wid;                // t0>>6 == tid>>5 (uniform/warp)
        const float* px = xs + t0;
        float* po = out + base + (unsigned)t0;
        #pragma unroll
        for (int i = 0; i < NI; ++i) {
            const float  tt = tau_time[i * NTB + blkb];  // broadcast LDS
            const float2 v  = *(const float2*)(px + i * CHUNK);
            float2 r;
            r.x = fmaxf(v.x - ta,  0.0f) * fmaxf(v.x - tt, 0.0f);
            r.y = fmaxf(v.y - tb2, 0.0f) * fmaxf(v.y - tt, 0.0f);
            *(float2*)(po + (unsigned)(i * NT)) = r;
        }
    }
}

extern "C" void kernel_launch(void* const* d_in, const int* in_sizes, int n_in,
                              void* d_out, int out_size)
{
    const float* in = (const float*)d_in[0];
    float* out = (float*)d_out;
    multiply_sparsemax_kernel<<<NB * NCHUNK, THREADS>>>(in, out);
}